// round 5
// baseline (speedup 1.0000x reference)
#include <cuda_runtime.h>
#include <math.h>

// Problem constants: B=4, L=512, E=1024, H=128
#define LL 512
#define EE 1024
#define HH 128
#define NB 4

// Scratch (device globals: no allocation allowed)
// g_hid: [2*B*L][H] = rec_hid rows 0..2047, lig_hid rows 2048..4095
__device__ float g_hid[4096 * HH];
__device__ float g_part[NB * 64];   // per (batch, 64x64 tile) partial max

__device__ __forceinline__ float fast_tanh(float x) {
    float y;
    asm("tanh.approx.f32 %0, %1;" : "=f"(y) : "f"(x));
    return y;
}

// ---------------------------------------------------------------------------
// Kernel 1: hid = relu(X @ W1 + b1)   (M=4096, K=1024, N=128)
// BM=64, BN=64, BK=16, 256 threads, 4x4 micro-tile.
// ---------------------------------------------------------------------------
__global__ __launch_bounds__(256) void gemm_hid_kernel(
    const float* __restrict__ rec, const float* __restrict__ lig,
    const float* __restrict__ W1, const float* __restrict__ b1)
{
    __shared__ __align__(16) float As[16][64];
    __shared__ __align__(16) float Bs[16][64];
    const int bx = blockIdx.x;   // h tile: 0..1
    const int by = blockIdx.y;   // m tile: 0..63
    const int tid = threadIdx.x;
    const int tx = tid & 15, ty = tid >> 4;

    // fill-role indices
    const int a_row = tid >> 2;          // 0..63
    const int a_e0  = (tid & 3) * 4;     // 0,4,8,12
    const int b_row = tid >> 4;          // 0..15
    const int b_h0  = (tid & 15) * 4;    // 0..60

    const int m_global = by * 64 + a_row;
    const float* src = (m_global < 2048)
        ? rec + (size_t)m_global * EE
        : lig + (size_t)(m_global - 2048) * EE;

    float c[4][4] = {};

    for (int kk = 0; kk < EE; kk += 16) {
        float4 av = *(const float4*)(src + kk + a_e0);
        float4 bv = *(const float4*)(W1 + (size_t)(kk + b_row) * HH + bx * 64 + b_h0);
        __syncthreads();
        As[a_e0 + 0][a_row] = av.x;
        As[a_e0 + 1][a_row] = av.y;
        As[a_e0 + 2][a_row] = av.z;
        As[a_e0 + 3][a_row] = av.w;
        *(float4*)&Bs[b_row][b_h0] = bv;
        __syncthreads();
        #pragma unroll
        for (int k = 0; k < 16; k++) {
            float4 ar = *(const float4*)&As[k][ty * 4];
            float4 br = *(const float4*)&Bs[k][tx * 4];
            float aa[4] = {ar.x, ar.y, ar.z, ar.w};
            float bb[4] = {br.x, br.y, br.z, br.w};
            #pragma unroll
            for (int i = 0; i < 4; i++)
                #pragma unroll
                for (int j = 0; j < 4; j++)
                    c[i][j] += aa[i] * bb[j];
        }
    }

    float4 bias = *(const float4*)(b1 + bx * 64 + tx * 4);
    float bb4[4] = {bias.x, bias.y, bias.z, bias.w};
    #pragma unroll
    for (int i = 0; i < 4; i++) {
        int m = by * 64 + ty * 4 + i;
        float4 o;
        o.x = fmaxf(c[i][0] + bb4[0], 0.f);
        o.y = fmaxf(c[i][1] + bb4[1], 0.f);
        o.z = fmaxf(c[i][2] + bb4[2], 0.f);
        o.w = fmaxf(c[i][3] + bb4[3], 0.f);
        *(float4*)&g_hid[(size_t)m * HH + bx * 64 + tx * 4] = o;
    }
}

// ---------------------------------------------------------------------------
// Kernel 2: fused tanh-outer-product + conv2x2 + max
// Each CTA: one batch, one 64x64 tile of y positions (p,q).
// Each thread: 4x4 y block via 5x5 tanh halo. H chunked 2x64 for smem.
// ---------------------------------------------------------------------------
#define RSTR 68   // 65 rows padded to 68 (multiple of 4 -> float4 aligned)

__global__ __launch_bounds__(256) void bilinear_max_kernel(
    const float* __restrict__ convw)
{
    __shared__ __align__(16) float rs[64 * RSTR];   // [h][row], r halo rows
    __shared__ __align__(16) float ls[64 * RSTR];   // [h][col], l halo cols
    __shared__ __align__(16) float ws[512];         // conv weights [h][2][2]
    __shared__ float red[256];

    const int b  = blockIdx.z;
    const int it = blockIdx.y;
    const int jt = blockIdx.x;
    const int tid = threadIdx.x;
    const int tx = tid & 15, ty = tid >> 4;
    const int i0 = it * 64, j0 = jt * 64;

    const float* rhid = g_hid + (size_t)(b * LL) * HH;
    const float* lhid = g_hid + (size_t)(2048 + b * LL) * HH;

    for (int idx = tid; idx < 512; idx += 256) ws[idx] = convw[idx];

    float acc[4][4] = {};

    for (int hc = 0; hc < 2; hc++) {
        __syncthreads();   // previous chunk fully consumed (and ws visible on hc=0)
        // fill halo tiles: 65 rows x 64 h each, transposed [h][row]
        for (int idx = tid; idx < 65 * 64; idx += 256) {
            int row = idx >> 6;
            int hh  = idx & 63;
            int gh  = hc * 64 + hh;
            int gi  = i0 - 1 + row;
            rs[hh * RSTR + row] = (gi >= 0) ? rhid[(size_t)gi * HH + gh] : 0.f;
            int gj  = j0 - 1 + row;
            ls[hh * RSTR + row] = (gj >= 0) ? lhid[(size_t)gj * HH + gh] : 0.f;
        }
        __syncthreads();

        #pragma unroll 1
        for (int hh = 0; hh < 64; hh++) {
            const float* rp = rs + hh * RSTR + 4 * ty;   // rows i0+4ty-1 .. +3
            const float* lp = ls + hh * RSTR + 4 * tx;
            float4 r4 = *(const float4*)rp;  float r5 = rp[4];
            float4 l4 = *(const float4*)lp;  float l5 = lp[4];
            float rr[5] = {r4.x, r4.y, r4.z, r4.w, r5};
            float llv[5] = {l4.x, l4.y, l4.z, l4.w, l5};
            float4 w4 = *(const float4*)(ws + (hc * 64 + hh) * 4);

            float t[5][5];
            #pragma unroll
            for (int u = 0; u < 5; u++)
                #pragma unroll
                for (int v = 0; v < 5; v++)
                    t[u][v] = fast_tanh(rr[u] * llv[v]);

            #pragma unroll
            for (int a = 0; a < 4; a++)
                #pragma unroll
                for (int q = 0; q < 4; q++)
                    acc[a][q] += w4.x * t[a][q]     + w4.y * t[a][q + 1]
                               + w4.z * t[a + 1][q] + w4.w * t[a + 1][q + 1];
        }
    }

    float m = acc[0][0];
    #pragma unroll
    for (int a = 0; a < 4; a++)
        #pragma unroll
        for (int q = 0; q < 4; q++)
            m = fmaxf(m, acc[a][q]);

    red[tid] = m;
    __syncthreads();
    #pragma unroll
    for (int s = 128; s > 0; s >>= 1) {
        if (tid < s) red[tid] = fmaxf(red[tid], red[tid + s]);
        __syncthreads();
    }
    if (tid == 0) g_part[b * 64 + it * 8 + jt] = red[0];
}

// ---------------------------------------------------------------------------
// Kernel 3: reduce 64 tile-maxes per batch, + conv_b, sigmoid
// ---------------------------------------------------------------------------
__global__ void finalize_kernel(const float* __restrict__ convb,
                                float* __restrict__ out)
{
    int w = threadIdx.x >> 5;     // warp id = batch
    int lane = threadIdx.x & 31;
    if (w < NB) {
        float m = fmaxf(g_part[w * 64 + lane], g_part[w * 64 + 32 + lane]);
        #pragma unroll
        for (int s = 16; s > 0; s >>= 1)
            m = fmaxf(m, __shfl_xor_sync(0xFFFFFFFFu, m, s));
        if (lane == 0) {
            float y = m + convb[0];
            out[w] = 1.f / (1.f + expf(-y));
        }
    }
}

extern "C" void kernel_launch(void* const* d_in, const int* in_sizes, int n_in,
                              void* d_out, int out_size)
{
    const float* rec   = (const float*)d_in[0];
    const float* lig   = (const float*)d_in[1];
    const float* W1    = (const float*)d_in[2];
    const float* b1    = (const float*)d_in[3];
    const float* convw = (const float*)d_in[4];
    const float* convb = (const float*)d_in[5];
    float* out = (float*)d_out;

    gemm_hid_kernel<<<dim3(2, 64), 256>>>(rec, lig, W1, b1);
    bilinear_max_kernel<<<dim3(8, 8, 4), 256>>>(convw);
    finalize_kernel<<<1, 128>>>(convb, out);
}

// round 7
// speedup vs baseline: 1.1625x; 1.1625x over previous
#include <cuda_runtime.h>
#include <math.h>

// Problem constants: B=4, L=512, E=1024, H=128
#define LL 512
#define EE 1024
#define HH 128
#define NB 4

// Scratch (device globals: no allocation allowed)
// g_hid: [2*B*L][H] = rec_hid rows 0..2047, lig_hid rows 2048..4095
__device__ float g_hid[4096 * HH];
__device__ float g_part[256];   // per (batch, tile) partial max (4*32 used)

__device__ __forceinline__ float fast_tanh(float x) {
    float y;
    asm("tanh.approx.f32 %0, %1;" : "=f"(y) : "f"(x));
    return y;
}

// ---------------------------------------------------------------------------
// Kernel 1: hid = relu(X @ W1 + b1)   (M=4096, K=1024, N=128)
// BM=64, BN=64, BK=16, 256 threads, 4x4 micro-tile.
// Double-buffered smem + register prefetch: global-load latency overlaps
// the FFMA mainloop (one __syncthreads per kk iteration).
// ---------------------------------------------------------------------------
__global__ __launch_bounds__(256) void gemm_hid_kernel(
    const float* __restrict__ rec, const float* __restrict__ lig,
    const float* __restrict__ W1, const float* __restrict__ b1)
{
    __shared__ __align__(16) float As[2][16][64];
    __shared__ __align__(16) float Bs[2][16][64];
    const int bx = blockIdx.x;   // h tile: 0..1
    const int by = blockIdx.y;   // m tile: 0..63
    const int tid = threadIdx.x;
    const int tx = tid & 15, ty = tid >> 4;

    // fill-role indices
    const int a_row = tid >> 2;          // 0..63
    const int a_e0  = (tid & 3) * 4;     // 0,4,8,12
    const int b_row = tid >> 4;          // 0..15
    const int b_h0  = (tid & 15) * 4;    // 0..60

    const int m_global = by * 64 + a_row;
    const float* src = (m_global < 2048)
        ? rec + (size_t)m_global * EE
        : lig + (size_t)(m_global - 2048) * EE;
    const float* wsrc = W1 + (size_t)b_row * HH + bx * 64 + b_h0;

    float c[4][4] = {};

    // prefetch tile 0
    float4 av = *(const float4*)(src + a_e0);
    float4 bv = *(const float4*)(wsrc);

    int buf = 0;
    for (int kk = 0; kk < 64; kk++) {
        // commit prefetched tile to smem[buf]
        As[buf][a_e0 + 0][a_row] = av.x;
        As[buf][a_e0 + 1][a_row] = av.y;
        As[buf][a_e0 + 2][a_row] = av.z;
        As[buf][a_e0 + 3][a_row] = av.w;
        *(float4*)&Bs[buf][b_row][b_h0] = bv;
        __syncthreads();

        // issue next tile's global loads; they complete during compute
        if (kk < 63) {
            av = *(const float4*)(src + (kk + 1) * 16 + a_e0);
            bv = *(const float4*)(wsrc + (size_t)(kk + 1) * 16 * HH);
        }

        #pragma unroll
        for (int k = 0; k < 16; k++) {
            float4 ar = *(const float4*)&As[buf][k][ty * 4];
            float4 br = *(const float4*)&Bs[buf][k][tx * 4];
            float aa[4] = {ar.x, ar.y, ar.z, ar.w};
            float bb[4] = {br.x, br.y, br.z, br.w};
            #pragma unroll
            for (int i = 0; i < 4; i++)
                #pragma unroll
                for (int j = 0; j < 4; j++)
                    c[i][j] += aa[i] * bb[j];
        }
        buf ^= 1;
        // no second sync needed: next iteration writes the OTHER buffer;
        // the write-after-read hazard on this buffer is two iterations away,
        // separated by the next iteration's __syncthreads.
    }

    float4 bias = *(const float4*)(b1 + bx * 64 + tx * 4);
    float bb4[4] = {bias.x, bias.y, bias.z, bias.w};
    #pragma unroll
    for (int i = 0; i < 4; i++) {
        int m = by * 64 + ty * 4 + i;
        float4 o;
        o.x = fmaxf(c[i][0] + bb4[0], 0.f);
        o.y = fmaxf(c[i][1] + bb4[1], 0.f);
        o.z = fmaxf(c[i][2] + bb4[2], 0.f);
        o.w = fmaxf(c[i][3] + bb4[3], 0.f);
        *(float4*)&g_hid[(size_t)m * HH + bx * 64 + tx * 4] = o;
    }
}

// ---------------------------------------------------------------------------
// Kernel 2: fused tanh-outer-product + conv2x2 + max
// CTA tile: 32 (i) x 256 (j). 256 threads: tx=tid&31 (8 cols each),
// ty=tid>>5 (4 rows each)  ->  r rows are WARP-UNIFORM, so the
// "r == 0 => whole tanh row is 0" skip is a uniform branch (no divergence,
// MUFUs genuinely not issued; ~50% of rows skip after ReLU).
// Per-thread 4x8 outputs via 5x9 tanh halo (1.41 tanh/output before skip).
// H chunked 4 x 32 to fit smem.
// ---------------------------------------------------------------------------
#define RST 36     // 33 halo rows padded
#define LST 260    // 257 halo cols padded

__global__ __launch_bounds__(256) void bilinear_max_kernel(
    const float* __restrict__ convw)
{
    __shared__ __align__(16) float rs[32 * RST];   // [h][halo row]
    __shared__ __align__(16) float ls[32 * LST];   // [h][halo col]
    __shared__ __align__(16) float ws4[512];       // conv weights [h][2][2]
    __shared__ float red[256];

    const int b  = blockIdx.z;
    const int it = blockIdx.y;     // 0..15
    const int jt = blockIdx.x;     // 0..1
    const int tid = threadIdx.x;
    const int tx = tid & 31;       // j-group: 8 cols
    const int ty = tid >> 5;       // i-group: 4 rows (warp-uniform)
    const int i0 = it * 32, j0 = jt * 256;

    const float* rhid = g_hid + (size_t)(b * LL) * HH;
    const float* lhid = g_hid + (size_t)(2048 + b * LL) * HH;

    for (int idx = tid; idx < 512; idx += 256) ws4[idx] = convw[idx];

    float acc[4][8] = {};

    for (int hc = 0; hc < 4; hc++) {
        __syncthreads();   // previous chunk fully consumed (and ws4 on hc=0)
        // fill halo tiles (transposed [h][pos]); zero-pad left edges
        for (int idx = tid; idx < 33 * 32; idx += 256) {
            int row = idx >> 5, hh = idx & 31;
            int gi = i0 - 1 + row;
            rs[hh * RST + row] = (gi >= 0) ? rhid[(size_t)gi * HH + hc * 32 + hh] : 0.f;
        }
        for (int idx = tid; idx < 257 * 32; idx += 256) {
            int col = idx >> 5, hh = idx & 31;
            int gj = j0 - 1 + col;
            ls[hh * LST + col] = (gj >= 0) ? lhid[(size_t)gj * HH + hc * 32 + hh] : 0.f;
        }
        __syncthreads();

        #pragma unroll 1
        for (int hh = 0; hh < 32; hh++) {
            const float* rp = rs + hh * RST + 4 * ty;   // halo rows 4ty..4ty+4
            const float* lp = ls + hh * LST + 8 * tx;   // halo cols 8tx..8tx+8
            float rr[5];
            #pragma unroll
            for (int r = 0; r < 5; r++) rr[r] = rp[r];  // warp-uniform -> bcast
            float4 la = *(const float4*)lp;
            float4 lb = *(const float4*)(lp + 4);
            float l8 = lp[8];
            float llv[9] = {la.x, la.y, la.z, la.w, lb.x, lb.y, lb.z, lb.w, l8};
            float4 w4 = *(const float4*)(ws4 + (hc * 32 + hh) * 4);

            #pragma unroll
            for (int u = 0; u < 5; u++) {
                float rv = rr[u];
                if (rv != 0.f) {            // warp-uniform branch (ReLU zeros)
                    float tr[9];
                    #pragma unroll
                    for (int v = 0; v < 9; v++) tr[v] = fast_tanh(rv * llv[v]);
                    if (u < 4) {            // t row u as dp=0 for output row u
                        #pragma unroll
                        for (int q = 0; q < 8; q++)
                            acc[u][q] += w4.x * tr[q] + w4.y * tr[q + 1];
                    }
                    if (u > 0) {            // t row u as dp=1 for output row u-1
                        #pragma unroll
                        for (int q = 0; q < 8; q++)
                            acc[u - 1][q] += w4.z * tr[q] + w4.w * tr[q + 1];
                    }
                }
            }
        }
    }

    float m = acc[0][0];
    #pragma unroll
    for (int a = 0; a < 4; a++)
        #pragma unroll
        for (int q = 0; q < 8; q++)
            m = fmaxf(m, acc[a][q]);

    red[tid] = m;
    __syncthreads();
    #pragma unroll
    for (int s = 128; s > 0; s >>= 1) {
        if (tid < s) red[tid] = fmaxf(red[tid], red[tid + s]);
        __syncthreads();
    }
    if (tid == 0) g_part[b * 32 + it * 2 + jt] = red[0];
}

// ---------------------------------------------------------------------------
// Kernel 3: reduce 32 tile-maxes per batch, + conv_b, sigmoid
// ---------------------------------------------------------------------------
__global__ void finalize_kernel(const float* __restrict__ convb,
                                float* __restrict__ out)
{
    int w = threadIdx.x >> 5;     // warp id = batch
    int lane = threadIdx.x & 31;
    if (w < NB) {
        float m = g_part[w * 32 + lane];
        #pragma unroll
        for (int s = 16; s > 0; s >>= 1)
            m = fmaxf(m, __shfl_xor_sync(0xFFFFFFFFu, m, s));
        if (lane == 0) {
            float y = m + convb[0];
            out[w] = 1.f / (1.f + expf(-y));
        }
    }
}

extern "C" void kernel_launch(void* const* d_in, const int* in_sizes, int n_in,
                              void* d_out, int out_size)
{
    const float* rec   = (const float*)d_in[0];
    const float* lig   = (const float*)d_in[1];
    const float* W1    = (const float*)d_in[2];
    const float* b1    = (const float*)d_in[3];
    const float* convw = (const float*)d_in[4];
    const float* convb = (const float*)d_in[5];
    float* out = (float*)d_out;

    gemm_hid_kernel<<<dim3(2, 64), 256>>>(rec, lig, W1, b1);
    bilinear_max_kernel<<<dim3(2, 16, 4), 256>>>(convw);
    finalize_kernel<<<1, 128>>>(convb, out);
}